// round 2
// baseline (speedup 1.0000x reference)
#include <cuda_runtime.h>
#include <math.h>

#define BB 4
#define NN 512
#define DD 128
#define TAU_INV 2.0f
#define EPSF 1e-9f

#define TI 16          // i rows per k_main block
#define TJ 32          // j tile
#define NTILE (NN/TJ)  // 16

// ---------------- scratch ----------------
__device__ float g_sj[BB * NN * DD];   // j-side: (ES@Wp+bp)@W1_src
__device__ float g_ti[BB * NN * DD];   // i-side: (ES@Wp+bp)@W1_tgt + b1

// ---------------- packed f32x2 helpers ----------------
__device__ __forceinline__ float2 fadd2(float2 a, float2 b) {
    float2 r;
    asm("{\n\t.reg .b64 ra, rb, rc;\n\t"
        "mov.b64 ra, {%2, %3};\n\t"
        "mov.b64 rb, {%4, %5};\n\t"
        "add.rn.f32x2 rc, ra, rb;\n\t"
        "mov.b64 {%0, %1}, rc;\n\t}"
        : "=f"(r.x), "=f"(r.y) : "f"(a.x), "f"(a.y), "f"(b.x), "f"(b.y));
    return r;
}
__device__ __forceinline__ float2 ffma2(float2 a, float2 b, float2 c) {
    float2 r;
    asm("{\n\t.reg .b64 ra, rb, rc;\n\t"
        "mov.b64 ra, {%2, %3};\n\t"
        "mov.b64 rb, {%4, %5};\n\t"
        "mov.b64 rc, {%6, %7};\n\t"
        "fma.rn.f32x2 rc, ra, rb, rc;\n\t"
        "mov.b64 {%0, %1}, rc;\n\t}"
        : "=f"(r.x), "=f"(r.y)
        : "f"(a.x), "f"(a.y), "f"(b.x), "f"(b.y), "f"(c.x), "f"(c.y));
    return r;
}

// ============ K1: fused combine+proj: s,t = (ES@Wp+bp)@W1_{src,tgt} (+b1) ============
#define PRT 16
__global__ void __launch_bounds__(256) k_proj(const float* __restrict__ ES,
                                              const float* __restrict__ Wp,
                                              const float* __restrict__ bp,
                                              const float* __restrict__ W1,
                                              const float* __restrict__ b1)
{
    __shared__ float es[PRT][DD];   // 8 KB
    __shared__ float pj[PRT][DD];   // 8 KB

    int tid = threadIdx.x;
    int mp  = tid & 63;     // m-pair: columns 2mp, 2mp+1
    int rg  = tid >> 6;     // 0..3 -> rows rg*4 .. rg*4+3
    int r0  = blockIdx.x * PRT;

    // stage ES rows
    {
        const float4* src = (const float4*)(ES + (size_t)r0 * DD);
        float4* dst = (float4*)&es[0][0];
        dst[tid]       = src[tid];
        dst[tid + 256] = src[tid + 256];
    }
    __syncthreads();

    // phase 1: proj = ES @ Wp + bp
    float2 acc[4];
    {
        float2 bp2 = *(const float2*)&bp[2 * mp];
        #pragma unroll
        for (int r = 0; r < 4; r++) acc[r] = bp2;
    }
    #pragma unroll 4
    for (int d = 0; d < DD; d += 4) {
        float4 e4[4];
        #pragma unroll
        for (int r = 0; r < 4; r++) e4[r] = *(const float4*)&es[rg * 4 + r][d];
        #pragma unroll
        for (int u = 0; u < 4; u++) {
            float2 w2 = *(const float2*)&Wp[(d + u) * DD + 2 * mp];
            float ev[4] = {0,0,0,0};
            ev[0] = (u==0)?e4[0].x:(u==1)?e4[0].y:(u==2)?e4[0].z:e4[0].w;
            ev[1] = (u==0)?e4[1].x:(u==1)?e4[1].y:(u==2)?e4[1].z:e4[1].w;
            ev[2] = (u==0)?e4[2].x:(u==1)?e4[2].y:(u==2)?e4[2].z:e4[2].w;
            ev[3] = (u==0)?e4[3].x:(u==1)?e4[3].y:(u==2)?e4[3].z:e4[3].w;
            #pragma unroll
            for (int r = 0; r < 4; r++)
                acc[r] = ffma2(make_float2(ev[r], ev[r]), w2, acc[r]);
        }
    }
    #pragma unroll
    for (int r = 0; r < 4; r++)
        *(float2*)&pj[rg * 4 + r][2 * mp] = acc[r];
    __syncthreads();

    // phase 2: s = proj @ W1_src ; t = proj @ W1_tgt + b1
    float2 as[4], at[4];
    {
        float2 b12 = *(const float2*)&b1[2 * mp];
        #pragma unroll
        for (int r = 0; r < 4; r++) { as[r] = make_float2(0.f, 0.f); at[r] = b12; }
    }
    #pragma unroll 4
    for (int d = 0; d < DD; d += 4) {
        float4 p4[4];
        #pragma unroll
        for (int r = 0; r < 4; r++) p4[r] = *(const float4*)&pj[rg * 4 + r][d];
        #pragma unroll
        for (int u = 0; u < 4; u++) {
            float2 ws = *(const float2*)&W1[(d + u) * DD + 2 * mp];
            float2 wt = *(const float2*)&W1[(d + u + DD) * DD + 2 * mp];
            float pv[4];
            pv[0] = (u==0)?p4[0].x:(u==1)?p4[0].y:(u==2)?p4[0].z:p4[0].w;
            pv[1] = (u==0)?p4[1].x:(u==1)?p4[1].y:(u==2)?p4[1].z:p4[1].w;
            pv[2] = (u==0)?p4[2].x:(u==1)?p4[2].y:(u==2)?p4[2].z:p4[2].w;
            pv[3] = (u==0)?p4[3].x:(u==1)?p4[3].y:(u==2)?p4[3].z:p4[3].w;
            #pragma unroll
            for (int r = 0; r < 4; r++) {
                float2 e2 = make_float2(pv[r], pv[r]);
                as[r] = ffma2(e2, ws, as[r]);
                at[r] = ffma2(e2, wt, at[r]);
            }
        }
    }
    #pragma unroll
    for (int r = 0; r < 4; r++) {
        int row = r0 + rg * 4 + r;
        *(float2*)&g_sj[(size_t)row * DD + 2 * mp] = as[r];
        *(float2*)&g_ti[(size_t)row * DD + 2 * mp] = at[r];
    }
}

// ============ K2: fused softmax + message aggregation + epilogue ============
// block: 256 thr; grid (32, 4). Each block: 16 i rows for one batch b.
extern __shared__ float dynsmem[];

__global__ void __launch_bounds__(256) k_main(const float* __restrict__ ES,
                                              const float* __restrict__ EL,
                                              const float* __restrict__ UN,
                                              const float* __restrict__ W2,
                                              const float* __restrict__ b2,
                                              float* __restrict__ out_state,
                                              float* __restrict__ out_A)
{
    float* sA = dynsmem;               // [16][512]  32 KB
    float* sS = sA + TI * NN;          // 2 x [32][128] 32 KB
    float* sV = sS + 2 * TJ * DD;      // [128][18]  9 KB (transposed v, pad 18)

    int tid  = threadIdx.x;
    int b    = blockIdx.y;
    int i0   = blockIdx.x * TI;

    // -------- phase A: Gumbel-softmax rows i0..i0+15, write sA + out_A --------
    {
        int warp = tid >> 5, lane = tid & 31;
        #pragma unroll
        for (int rr = 0; rr < 2; rr++) {
            int r = warp * 2 + rr;
            int i = i0 + r;
            const float* elp = EL + (size_t)i * NN;
            const float* up  = UN + (size_t)i * NN;
            float xv[16];
            float mx = -1e30f;
            #pragma unroll
            for (int c = 0; c < 16; c++) {
                int j = c * 32 + lane;
                float inner = logf(up[j] + EPSF);       // precise (arg can be ~1)
                float g = -__logf(-inner + EPSF);       // fast ok here
                float x = (elp[j] + g) * TAU_INV;
                xv[c] = x;
                mx = fmaxf(mx, x);
            }
            #pragma unroll
            for (int o = 16; o > 0; o >>= 1) mx = fmaxf(mx, __shfl_xor_sync(0xffffffffu, mx, o));
            float s = 0.f;
            #pragma unroll
            for (int c = 0; c < 16; c++) { float e = __expf(xv[c] - mx); xv[c] = e; s += e; }
            #pragma unroll
            for (int o = 16; o > 0; o >>= 1) s += __shfl_xor_sync(0xffffffffu, s, o);
            float rinv = 1.0f / s;
            float* arow = sA + r * NN;
            float* oA   = out_A + ((size_t)b * NN + i) * NN;
            #pragma unroll
            for (int c = 0; c < 16; c++) {
                int j = c * 32 + lane;
                float a = xv[c] * rinv;
                arow[j] = a;
                oA[j]   = a;
            }
        }
    }
    __syncthreads();

    // -------- phase B: v[i,k] = sum_j A[i,j] * relu(t_i[k] + s_j[k]) --------
    int kp = tid & 63;     // k-pair
    int ig = tid >> 6;     // 0..3 -> i rows ig*4..ig*4+3

    float2 tv[4], acc[4];
    #pragma unroll
    for (int r = 0; r < 4; r++) {
        tv[r]  = *(const float2*)&g_ti[((size_t)(b * NN + i0 + ig * 4 + r)) * DD + 2 * kp];
        acc[r] = make_float2(0.f, 0.f);
    }

    const float4* sb4 = (const float4*)(g_sj + (size_t)b * NN * DD);
    float4 pf[4];
    #pragma unroll
    for (int q = 0; q < 4; q++) pf[q] = sb4[tid + q * 256];   // tile 0

    for (int t = 0; t < NTILE; t++) {
        float* buf = sS + (t & 1) * (TJ * DD);
        float4* bd = (float4*)buf;
        #pragma unroll
        for (int q = 0; q < 4; q++) bd[tid + q * 256] = pf[q];
        if (t < NTILE - 1) {
            #pragma unroll
            for (int q = 0; q < 4; q++) pf[q] = sb4[(t + 1) * (TJ * DD / 4) + tid + q * 256];
        }
        __syncthreads();

        const float* a0 = sA + (ig * 4 + 0) * NN + t * TJ;
        const float* a1 = sA + (ig * 4 + 1) * NN + t * TJ;
        const float* a2 = sA + (ig * 4 + 2) * NN + t * TJ;
        const float* a3 = sA + (ig * 4 + 3) * NN + t * TJ;

        #pragma unroll
        for (int jj = 0; jj < TJ; jj += 4) {
            float4 av0 = *(const float4*)(a0 + jj);
            float4 av1 = *(const float4*)(a1 + jj);
            float4 av2 = *(const float4*)(a2 + jj);
            float4 av3 = *(const float4*)(a3 + jj);
            #pragma unroll
            for (int u = 0; u < 4; u++) {
                float2 sv = *(const float2*)(buf + (jj + u) * DD + 2 * kp);
                float aa0 = (u==0)?av0.x:(u==1)?av0.y:(u==2)?av0.z:av0.w;
                float aa1 = (u==0)?av1.x:(u==1)?av1.y:(u==2)?av1.z:av1.w;
                float aa2 = (u==0)?av2.x:(u==1)?av2.y:(u==2)?av2.z:av2.w;
                float aa3 = (u==0)?av3.x:(u==1)?av3.y:(u==2)?av3.z:av3.w;
                float2 x;
                x = fadd2(sv, tv[0]); x.x = fmaxf(x.x, 0.f); x.y = fmaxf(x.y, 0.f);
                acc[0] = ffma2(make_float2(aa0, aa0), x, acc[0]);
                x = fadd2(sv, tv[1]); x.x = fmaxf(x.x, 0.f); x.y = fmaxf(x.y, 0.f);
                acc[1] = ffma2(make_float2(aa1, aa1), x, acc[1]);
                x = fadd2(sv, tv[2]); x.x = fmaxf(x.x, 0.f); x.y = fmaxf(x.y, 0.f);
                acc[2] = ffma2(make_float2(aa2, aa2), x, acc[2]);
                x = fadd2(sv, tv[3]); x.x = fmaxf(x.x, 0.f); x.y = fmaxf(x.y, 0.f);
                acc[3] = ffma2(make_float2(aa3, aa3), x, acc[3]);
            }
        }
        __syncthreads();
    }

    // -------- stash v transposed: sV[k][il], pad 18 --------
    #pragma unroll
    for (int r = 0; r < 4; r++) {
        int il = ig * 4 + r;
        sV[(2 * kp + 0) * 18 + il] = acc[r].x;
        sV[(2 * kp + 1) * 18 + il] = acc[r].y;
    }
    __syncthreads();

    // -------- epilogue: out = ES + v @ W2 + b2 --------
    {
        int m  = tid & 127;
        int gq = tid >> 7;             // 0..1 -> i rows gq*8..gq*8+7 (as 4 pairs)
        float2 o2[4];
        #pragma unroll
        for (int ii = 0; ii < 4; ii++) o2[ii] = make_float2(0.f, 0.f);
        #pragma unroll 4
        for (int k = 0; k < DD; k++) {
            float w = __ldg(&W2[k * DD + m]);
            float2 wb = make_float2(w, w);
            const float* vr = sV + k * 18 + gq * 8;
            #pragma unroll
            for (int ii = 0; ii < 4; ii++) {
                float2 v2 = *(const float2*)(vr + 2 * ii);
                o2[ii] = ffma2(v2, wb, o2[ii]);
            }
        }
        float b2v = b2[m];
        #pragma unroll
        for (int ii = 0; ii < 4; ii++) {
            int i = i0 + gq * 8 + 2 * ii;
            size_t base = ((size_t)b * NN + i) * DD + m;
            out_state[base]      = ES[base]      + o2[ii].x + b2v;
            out_state[base + DD] = ES[base + DD] + o2[ii].y + b2v;
        }
    }
}

// ---------------- launch ----------------
extern "C" void kernel_launch(void* const* d_in, const int* in_sizes, int n_in,
                              void* d_out, int out_size)
{
    const float* ES  = (const float*)d_in[0];   // (B,N,D)
    const float* Wp  = (const float*)d_in[1];   // (D,D)
    const float* bp  = (const float*)d_in[2];   // (D,)
    const float* EL  = (const float*)d_in[3];   // (N,N)
    const float* W1  = (const float*)d_in[4];   // (2D,D)
    const float* b1  = (const float*)d_in[5];   // (D,)
    const float* W2  = (const float*)d_in[6];   // (D,D)
    const float* b2  = (const float*)d_in[7];   // (D,)
    const float* UN  = (const float*)d_in[8];   // (N,N)

    float* out_state = (float*)d_out;
    float* out_A     = (float*)d_out + (size_t)BB * NN * DD;

    static const int SMEM_MAIN = (TI * NN + 2 * TJ * DD + DD * 18) * 4;  // ~75 KB
    cudaFuncSetAttribute(k_main, cudaFuncAttributeMaxDynamicSharedMemorySize, SMEM_MAIN);

    k_proj<<<(BB * NN) / PRT, 256>>>(ES, Wp, bp, W1, b1);
    k_main<<<dim3(NN / TI, BB), 256, SMEM_MAIN>>>(ES, EL, UN, W2, b2, out_state, out_A);
}

// round 3
// speedup vs baseline: 1.2270x; 1.2270x over previous
#include <cuda_runtime.h>
#include <math.h>

#define BB 4
#define NN 512
#define DD 128
#define TAU_INV 2.0f
#define EPSF 1e-9f

#define TI 16            // i rows per k_main block
#define JS 4             // j splits
#define JR (NN/JS)       // 128 j's per block
#define TJ 32            // j tile staged in shared
#define PRT 8            // rows per k_proj block
#define ERT 8            // rows per k_epi block

// ---------------- scratch ----------------
__device__ float g_sj[BB * NN * DD];          // (ES@Wp+bp)@W1_src
__device__ float g_ti[BB * NN * DD];          // (ES@Wp+bp)@W1_tgt + b1
__device__ float g_v [JS * BB * NN * DD];     // partial v per j-split (4 MB)

// ---------------- fused relu-mad on packed f32x2 ----------------
// acc += a * relu(s + t), 4 lanes (2 b64 packs), all operands b64 in regs.
__device__ __forceinline__ void relu_mad4(unsigned long long& acc0, unsigned long long& acc1,
                                          unsigned long long s0, unsigned long long s1,
                                          unsigned long long t0, unsigned long long t1,
                                          unsigned long long a2)
{
    asm("{\n\t"
        ".reg .b64 x0, x1;\n\t"
        ".reg .f32 l0, h0, l1, h1;\n\t"
        "add.rn.f32x2 x0, %2, %4;\n\t"
        "add.rn.f32x2 x1, %3, %5;\n\t"
        "mov.b64 {l0, h0}, x0;\n\t"
        "mov.b64 {l1, h1}, x1;\n\t"
        "max.f32 l0, l0, 0f00000000;\n\t"
        "max.f32 h0, h0, 0f00000000;\n\t"
        "max.f32 l1, l1, 0f00000000;\n\t"
        "max.f32 h1, h1, 0f00000000;\n\t"
        "mov.b64 x0, {l0, h0};\n\t"
        "mov.b64 x1, {l1, h1};\n\t"
        "fma.rn.f32x2 %0, x0, %6, %0;\n\t"
        "fma.rn.f32x2 %1, x1, %6, %1;\n\t"
        "}"
        : "+l"(acc0), "+l"(acc1)
        : "l"(s0), "l"(s1), "l"(t0), "l"(t1), "l"(a2));
}

__device__ __forceinline__ unsigned long long bcast2(float a) {
    unsigned long long r;
    asm("mov.b64 %0, {%1, %1};" : "=l"(r) : "f"(a));
    return r;
}

// ============ K1: s,t = (ES@Wp+bp)@W1_{src,tgt} (+b1), fused combine ============
__global__ void __launch_bounds__(256) k_proj(const float* __restrict__ ES,
                                              const float* __restrict__ Wp,
                                              const float* __restrict__ bp,
                                              const float* __restrict__ W1,
                                              const float* __restrict__ b1)
{
    __shared__ float es[PRT * DD];   // 4 KB
    __shared__ float pj[PRT * DD];   // 4 KB
    int tid = threadIdx.x;
    int m   = tid & 127;
    int hf  = tid >> 7;              // rows hf*4 .. hf*4+3
    int r0  = blockIdx.x * PRT;

    ((float4*)es)[tid] = ((const float4*)(ES + (size_t)r0 * DD))[tid];
    __syncthreads();

    // phase 1: proj = ES @ Wp + bp
    float acc[4];
    {
        float bpv = bp[m];
        #pragma unroll
        for (int r = 0; r < 4; r++) acc[r] = bpv;
    }
    #pragma unroll 4
    for (int d = 0; d < DD; d++) {
        float w = Wp[d * DD + m];
        #pragma unroll
        for (int r = 0; r < 4; r++) acc[r] += es[(hf * 4 + r) * DD + d] * w;
    }
    #pragma unroll
    for (int r = 0; r < 4; r++) pj[(hf * 4 + r) * DD + m] = acc[r];
    __syncthreads();

    // phase 2: s = proj@W1_src, t = proj@W1_tgt + b1
    float as[4], at[4];
    {
        float b1v = b1[m];
        #pragma unroll
        for (int r = 0; r < 4; r++) { as[r] = 0.f; at[r] = b1v; }
    }
    #pragma unroll 4
    for (int d = 0; d < DD; d++) {
        float ws = W1[d * DD + m];
        float wt = W1[(d + DD) * DD + m];
        #pragma unroll
        for (int r = 0; r < 4; r++) {
            float p = pj[(hf * 4 + r) * DD + d];
            as[r] += p * ws;
            at[r] += p * wt;
        }
    }
    #pragma unroll
    for (int r = 0; r < 4; r++) {
        size_t row = (size_t)(r0 + hf * 4 + r);
        g_sj[row * DD + m] = as[r];
        g_ti[row * DD + m] = at[r];
    }
}

// ============ K2: fused gumbel-softmax + partial message aggregation ============
// grid (NN/TI=32, BB=4, JS=4); 256 threads; 24 KB static smem.
__global__ void __launch_bounds__(256, 4) k_main(const float* __restrict__ EL,
                                                 const float* __restrict__ UN,
                                                 float* __restrict__ out_A)
{
    __shared__ float sA[TI * JR];    // 8 KB : A slice for this j-split
    __shared__ float sS[TJ * DD];    // 16 KB : s tile

    int tid = threadIdx.x;
    int b   = blockIdx.y;
    int i0  = blockIdx.x * TI;
    int js  = blockIdx.z;

    // -------- phase A: gumbel-softmax rows i0..i0+15 (full row; keep js slice) ------
    {
        int warp = tid >> 5, lane = tid & 31;
        #pragma unroll
        for (int rr = 0; rr < 2; rr++) {
            int r = warp * 2 + rr;
            int i = i0 + r;
            const float* elp = EL + (size_t)i * NN;
            const float* up  = UN + (size_t)i * NN;
            float xv[16];
            float mx = -1e30f;
            #pragma unroll
            for (int c = 0; c < 16; c++) {
                int j = c * 32 + lane;
                float inner = logf(up[j] + EPSF);        // precise: arg near 1
                float g = -__logf(-inner + EPSF);
                float x = (elp[j] + g) * TAU_INV;
                xv[c] = x;
                mx = fmaxf(mx, x);
            }
            #pragma unroll
            for (int o = 16; o > 0; o >>= 1) mx = fmaxf(mx, __shfl_xor_sync(0xffffffffu, mx, o));
            float s = 0.f;
            #pragma unroll
            for (int c = 0; c < 16; c++) { float e = __expf(xv[c] - mx); xv[c] = e; s += e; }
            #pragma unroll
            for (int o = 16; o > 0; o >>= 1) s += __shfl_xor_sync(0xffffffffu, s, o);
            float rinv = 1.0f / s;
            float* oA = out_A + ((size_t)b * NN + i) * NN;
            #pragma unroll
            for (int c = 0; c < 16; c++) {
                float a = xv[c] * rinv;
                if ((c >> 2) == js) sA[r * JR + (c & 3) * 32 + lane] = a;
                if (js == 0) oA[c * 32 + lane] = a;
            }
        }
    }
    __syncthreads();

    // -------- phase B: v_partial[i,k] = sum_{j in slice} A[i,j]*relu(t_i[k]+s_j[k]) --
    int kq = tid & 31;       // k quad: k = kq*4
    int ig = tid >> 5;       // warp id 0..7 -> i rows ig*2, ig*2+1
    int iA = ig * 2, iB = ig * 2 + 1;

    ulonglong2 tA = *(const ulonglong2*)&g_ti[((size_t)(b * NN + i0 + iA)) * DD + kq * 4];
    ulonglong2 tB = *(const ulonglong2*)&g_ti[((size_t)(b * NN + i0 + iB)) * DD + kq * 4];
    unsigned long long accA0 = 0ull, accA1 = 0ull, accB0 = 0ull, accB1 = 0ull;

    const float4* sb4 = (const float4*)(g_sj + ((size_t)b * NN + js * JR) * DD);

    #pragma unroll 1
    for (int t = 0; t < JR / TJ; t++) {
        #pragma unroll
        for (int q = 0; q < 4; q++)
            ((float4*)sS)[tid + q * 256] = sb4[t * (TJ * DD / 4) + tid + q * 256];
        __syncthreads();

        const float* arA = sA + iA * JR + t * TJ;
        const float* arB = sA + iB * JR + t * TJ;

        #pragma unroll 4
        for (int jj = 0; jj < TJ; jj += 2) {
            float2 avA = *(const float2*)(arA + jj);
            float2 avB = *(const float2*)(arB + jj);
            {
                ulonglong2 sv = *(const ulonglong2*)&sS[jj * DD + kq * 4];
                unsigned long long aA = bcast2(avA.x);
                unsigned long long aB = bcast2(avB.x);
                relu_mad4(accA0, accA1, sv.x, sv.y, tA.x, tA.y, aA);
                relu_mad4(accB0, accB1, sv.x, sv.y, tB.x, tB.y, aB);
            }
            {
                ulonglong2 sv = *(const ulonglong2*)&sS[(jj + 1) * DD + kq * 4];
                unsigned long long aA = bcast2(avA.y);
                unsigned long long aB = bcast2(avB.y);
                relu_mad4(accA0, accA1, sv.x, sv.y, tA.x, tA.y, aA);
                relu_mad4(accB0, accB1, sv.x, sv.y, tB.x, tB.y, aB);
            }
        }
        __syncthreads();
    }

    // -------- write partial v: layout [js][b][i][k] --------
    {
        ulonglong2 oA; oA.x = accA0; oA.y = accA1;
        ulonglong2 oB; oB.x = accB0; oB.y = accB1;
        size_t base = (((size_t)js * BB + b) * NN + i0) * DD;
        *(ulonglong2*)&g_v[base + (size_t)iA * DD + kq * 4] = oA;
        *(ulonglong2*)&g_v[base + (size_t)iB * DD + kq * 4] = oB;
    }
}

// ============ K3: out = ES + (sum_js v) @ W2 + b2 ============
__global__ void __launch_bounds__(256) k_epi(const float* __restrict__ ES,
                                             const float* __restrict__ W2,
                                             const float* __restrict__ b2,
                                             float* __restrict__ out_state)
{
    __shared__ float sv[ERT * DD];   // 4 KB
    int tid  = threadIdx.x;
    size_t row0 = (size_t)blockIdx.x * ERT;   // flat row in B*N

    // sum the 4 j-split partials (1 float4 per thread)
    {
        size_t off = row0 * DD / 4 + tid;
        float4 a = ((const float4*)g_v)[off];
        float4 c = ((const float4*)g_v)[off + 1 * (size_t)BB * NN * DD / 4];
        float4 d = ((const float4*)g_v)[off + 2 * (size_t)BB * NN * DD / 4];
        float4 e = ((const float4*)g_v)[off + 3 * (size_t)BB * NN * DD / 4];
        a.x += c.x; a.y += c.y; a.z += c.z; a.w += c.w;
        d.x += e.x; d.y += e.y; d.z += e.z; d.w += e.w;
        a.x += d.x; a.y += d.y; a.z += d.z; a.w += d.w;
        ((float4*)sv)[tid] = a;
    }
    __syncthreads();

    int m  = tid & 127;
    int gq = tid >> 7;               // rows gq*4 .. gq*4+3
    float o[4] = {0.f, 0.f, 0.f, 0.f};
    #pragma unroll 4
    for (int k = 0; k < DD; k++) {
        float w = W2[k * DD + m];
        #pragma unroll
        for (int r = 0; r < 4; r++) o[r] += sv[(gq * 4 + r) * DD + k] * w;
    }
    float bb = b2[m];
    #pragma unroll
    for (int r = 0; r < 4; r++) {
        size_t base = (row0 + gq * 4 + r) * DD + m;
        out_state[base] = ES[base] + o[r] + bb;
    }
}

// ---------------- launch ----------------
extern "C" void kernel_launch(void* const* d_in, const int* in_sizes, int n_in,
                              void* d_out, int out_size)
{
    const float* ES  = (const float*)d_in[0];   // (B,N,D)
    const float* Wp  = (const float*)d_in[1];   // (D,D)
    const float* bp  = (const float*)d_in[2];   // (D,)
    const float* EL  = (const float*)d_in[3];   // (N,N)
    const float* W1  = (const float*)d_in[4];   // (2D,D)
    const float* b1  = (const float*)d_in[5];   // (D,)
    const float* W2  = (const float*)d_in[6];   // (D,D)
    const float* b2  = (const float*)d_in[7];   // (D,)
    const float* UN  = (const float*)d_in[8];   // (N,N)

    float* out_state = (float*)d_out;
    float* out_A     = (float*)d_out + (size_t)BB * NN * DD;

    k_proj<<<(BB * NN) / PRT, 256>>>(ES, Wp, bp, W1, b1);
    k_main<<<dim3(NN / TI, BB, JS), 256>>>(EL, UN, out_A);
    k_epi<<<(BB * NN) / ERT, 256>>>(ES, W2, b2, out_state);
}

// round 6
// speedup vs baseline: 1.5460x; 1.2600x over previous
#include <cuda_runtime.h>
#include <math.h>

#define BB 4
#define NN 512
#define DD 128
#define TAU_INV 2.0f
#define EPSF 1e-9f

#define TI 16            // i rows per k_main block
#define JS 4             // j splits
#define JR (NN/JS)       // 128 j's per block
#define TJ 32            // j tile staged in shared

#define GBM 64
#define GBN 64
#define GBK 32
#define APAD 4           // pad so row stride (GBM+APAD)*4B is 16B-aligned

// ---------------- scratch ----------------
__device__ float g_sj[BB * NN * DD];          // (ES@Wp+bp)@W1_src + Bc_s
__device__ float g_ti[BB * NN * DD];          // (ES@Wp+bp)@W1_tgt + Bc_t (b1 folded)
__device__ float g_v [JS * BB * NN * DD];     // partial v per j-split (4 MB)
__device__ float g_Wc[DD * 256];              // combined weights [d][col], col<128 src
__device__ float g_Bc[256];                   // combined bias

// ---------------- packed f32x2 helpers ----------------
__device__ __forceinline__ void fma2acc(unsigned long long& acc,
                                        unsigned long long a, unsigned long long b) {
    asm("fma.rn.f32x2 %0, %1, %2, %0;" : "+l"(acc) : "l"(a), "l"(b));
}
__device__ __forceinline__ unsigned long long bcast2(float a) {
    unsigned long long r;
    asm("mov.b64 %0, {%1, %1};" : "=l"(r) : "f"(a));
    return r;
}
__device__ __forceinline__ float2 unpack2(unsigned long long v) {
    float2 r;
    asm("mov.b64 {%0, %1}, %2;" : "=f"(r.x), "=f"(r.y) : "l"(v));
    return r;
}
// acc += a * relu(s + t), 4 lanes (2 b64 packs)
__device__ __forceinline__ void relu_mad4(unsigned long long& acc0, unsigned long long& acc1,
                                          unsigned long long s0, unsigned long long s1,
                                          unsigned long long t0, unsigned long long t1,
                                          unsigned long long a2)
{
    asm("{\n\t"
        ".reg .b64 x0, x1;\n\t"
        ".reg .f32 l0, h0, l1, h1;\n\t"
        "add.rn.f32x2 x0, %2, %4;\n\t"
        "add.rn.f32x2 x1, %3, %5;\n\t"
        "mov.b64 {l0, h0}, x0;\n\t"
        "mov.b64 {l1, h1}, x1;\n\t"
        "max.f32 l0, l0, 0f00000000;\n\t"
        "max.f32 h0, h0, 0f00000000;\n\t"
        "max.f32 l1, l1, 0f00000000;\n\t"
        "max.f32 h1, h1, 0f00000000;\n\t"
        "mov.b64 x0, {l0, h0};\n\t"
        "mov.b64 x1, {l1, h1};\n\t"
        "fma.rn.f32x2 %0, x0, %6, %0;\n\t"
        "fma.rn.f32x2 %1, x1, %6, %1;\n\t"
        "}"
        : "+l"(acc0), "+l"(acc1)
        : "l"(s0), "l"(s1), "l"(t0), "l"(t1), "l"(a2));
}

// ============ K0: Wc = Wp @ [W1s|W1t];  Bc = bp @ [W1s|W1t] (+b1 tgt half) ============
__global__ void __launch_bounds__(256) k_combine(const float* __restrict__ Wp,
                                                 const float* __restrict__ bp,
                                                 const float* __restrict__ W1,
                                                 const float* __restrict__ b1)
{
    __shared__ float wp[DD];
    int col  = threadIdx.x;          // 0..255
    int d    = blockIdx.x;           // 0..128 (last block: biases)
    int half = col >> 7;
    int m    = col & 127;
    const float* base = W1 + (size_t)(half ? DD * DD : 0) + m;

    if (d < DD) {
        if (col < DD) wp[col] = Wp[d * DD + col];
        __syncthreads();
        float acc = 0.f;
        #pragma unroll 8
        for (int k = 0; k < DD; k++) acc += wp[k] * base[(size_t)k * DD];
        g_Wc[d * 256 + col] = acc;
    } else {
        float acc = half ? b1[m] : 0.f;
        #pragma unroll 8
        for (int k = 0; k < DD; k++) acc += bp[k] * base[(size_t)k * DD];
        g_Bc[col] = acc;
    }
}

// ============ K1: tiled GEMM: [s|t] = ES @ Wc + Bc ============
__global__ void __launch_bounds__(256) k_proj(const float* __restrict__ ES)
{
    __shared__ float sE[GBK][GBM + APAD];   // transposed: sE[k][row]
    __shared__ float sW[GBK][GBN];

    int tid = threadIdx.x;
    int tx  = tid & 15;                  // col group: cols tx*4..tx*4+3
    int ty  = tid >> 4;                  // row group: rows ty*4..ty*4+3
    int r0  = blockIdx.x * GBM;
    int c0  = blockIdx.y * GBN;

    int lrow = tid >> 3;                 // 0..31
    int lk4  = tid & 7;                  // 0..7
    int wk   = tid >> 4;                 // 0..15
    int wc4  = tid & 15;                 // 0..15

    float4 eA[2], wB[2];
    {
        const float* ep = ES + (size_t)r0 * DD;
        eA[0] = *(const float4*)&ep[(lrow     ) * DD + lk4 * 4];
        eA[1] = *(const float4*)&ep[(lrow + 32) * DD + lk4 * 4];
        const float* wpg = g_Wc + c0;
        wB[0] = *(const float4*)&wpg[(wk     ) * 256 + wc4 * 4];
        wB[1] = *(const float4*)&wpg[(wk + 16) * 256 + wc4 * 4];
    }

    unsigned long long acc[4][2];
    #pragma unroll
    for (int r = 0; r < 4; r++) { acc[r][0] = 0ull; acc[r][1] = 0ull; }

    for (int kt = 0; kt < DD; kt += GBK) {
        if (kt) __syncthreads();
        #pragma unroll
        for (int q = 0; q < 2; q++) {
            sE[lk4 * 4 + 0][lrow + q * 32] = (&eA[q].x)[0];
            sE[lk4 * 4 + 1][lrow + q * 32] = (&eA[q].x)[1];
            sE[lk4 * 4 + 2][lrow + q * 32] = (&eA[q].x)[2];
            sE[lk4 * 4 + 3][lrow + q * 32] = (&eA[q].x)[3];
        }
        *(float4*)&sW[wk][wc4 * 4]      = wB[0];
        *(float4*)&sW[wk + 16][wc4 * 4] = wB[1];
        __syncthreads();

        if (kt + GBK < DD) {
            const float* ep = ES + (size_t)r0 * DD + (kt + GBK);
            eA[0] = *(const float4*)&ep[(lrow     ) * DD + lk4 * 4];
            eA[1] = *(const float4*)&ep[(lrow + 32) * DD + lk4 * 4];
            const float* wpg = g_Wc + c0 + (size_t)(kt + GBK) * 256;
            wB[0] = *(const float4*)&wpg[(wk     ) * 256 + wc4 * 4];
            wB[1] = *(const float4*)&wpg[(wk + 16) * 256 + wc4 * 4];
        }

        #pragma unroll 8
        for (int k = 0; k < GBK; k++) {
            float4 e4 = *(const float4*)&sE[k][ty * 4];
            ulonglong2 w2 = *(const ulonglong2*)&sW[k][tx * 4];
            unsigned long long e0 = bcast2(e4.x);
            unsigned long long e1 = bcast2(e4.y);
            unsigned long long e2 = bcast2(e4.z);
            unsigned long long e3 = bcast2(e4.w);
            fma2acc(acc[0][0], e0, w2.x); fma2acc(acc[0][1], e0, w2.y);
            fma2acc(acc[1][0], e1, w2.x); fma2acc(acc[1][1], e1, w2.y);
            fma2acc(acc[2][0], e2, w2.x); fma2acc(acc[2][1], e2, w2.y);
            fma2acc(acc[3][0], e3, w2.x); fma2acc(acc[3][1], e3, w2.y);
        }
    }

    float4 bias = *(const float4*)&g_Bc[c0 + tx * 4];
    float* dst = (c0 < DD) ? g_sj : g_ti;
    int    mc  = (c0 < DD) ? c0 : (c0 - DD);
    #pragma unroll
    for (int r = 0; r < 4; r++) {
        int row = r0 + ty * 4 + r;
        float2 p0 = unpack2(acc[r][0]);
        float2 p1 = unpack2(acc[r][1]);
        float4 o;
        o.x = p0.x + bias.x; o.y = p0.y + bias.y;
        o.z = p1.x + bias.z; o.w = p1.y + bias.w;
        *(float4*)&dst[(size_t)row * DD + mc + tx * 4] = o;
    }
}

// ============ K2: fused gumbel-softmax + partial message aggregation ============
__global__ void __launch_bounds__(256, 4) k_main(const float* __restrict__ EL,
                                                 const float* __restrict__ UN,
                                                 float* __restrict__ out_A)
{
    __shared__ float sA[TI * JR];    // 8 KB
    __shared__ float sS[TJ * DD];    // 16 KB

    int tid = threadIdx.x;
    int b   = blockIdx.y;
    int i0  = blockIdx.x * TI;
    int js  = blockIdx.z;

    // phase A: gumbel-softmax rows i0..i0+15
    {
        int warp = tid >> 5, lane = tid & 31;
        #pragma unroll
        for (int rr = 0; rr < 2; rr++) {
            int r = warp * 2 + rr;
            int i = i0 + r;
            const float* elp = EL + (size_t)i * NN;
            const float* up  = UN + (size_t)i * NN;
            float xv[16];
            float mx = -1e30f;
            #pragma unroll
            for (int c = 0; c < 16; c++) {
                int j = c * 32 + lane;
                float inner = logf(up[j] + EPSF);
                float g = -__logf(-inner + EPSF);
                float x = (elp[j] + g) * TAU_INV;
                xv[c] = x;
                mx = fmaxf(mx, x);
            }
            #pragma unroll
            for (int o = 16; o > 0; o >>= 1) mx = fmaxf(mx, __shfl_xor_sync(0xffffffffu, mx, o));
            float s = 0.f;
            #pragma unroll
            for (int c = 0; c < 16; c++) { float e = __expf(xv[c] - mx); xv[c] = e; s += e; }
            #pragma unroll
            for (int o = 16; o > 0; o >>= 1) s += __shfl_xor_sync(0xffffffffu, s, o);
            float rinv = 1.0f / s;
            float* oA = out_A + ((size_t)b * NN + i) * NN;
            #pragma unroll
            for (int c = 0; c < 16; c++) {
                float a = xv[c] * rinv;
                if ((c >> 2) == js) sA[r * JR + (c & 3) * 32 + lane] = a;
                if (js == 0) oA[c * 32 + lane] = a;
            }
        }
    }
    __syncthreads();

    // phase B
    int kq = tid & 31;
    int ig = tid >> 5;
    int iA = ig * 2, iB = ig * 2 + 1;

    ulonglong2 tA = *(const ulonglong2*)&g_ti[((size_t)(b * NN + i0 + iA)) * DD + kq * 4];
    ulonglong2 tB = *(const ulonglong2*)&g_ti[((size_t)(b * NN + i0 + iB)) * DD + kq * 4];
    unsigned long long accA0 = 0ull, accA1 = 0ull, accB0 = 0ull, accB1 = 0ull;

    const float4* sb4 = (const float4*)(g_sj + ((size_t)b * NN + js * JR) * DD);

    #pragma unroll 1
    for (int t = 0; t < JR / TJ; t++) {
        #pragma unroll
        for (int q = 0; q < 4; q++)
            ((float4*)sS)[tid + q * 256] = sb4[t * (TJ * DD / 4) + tid + q * 256];
        __syncthreads();

        const float* arA = sA + iA * JR + t * TJ;
        const float* arB = sA + iB * JR + t * TJ;

        #pragma unroll 4
        for (int jj = 0; jj < TJ; jj += 2) {
            float2 avA = *(const float2*)(arA + jj);
            float2 avB = *(const float2*)(arB + jj);
            {
                ulonglong2 sv = *(const ulonglong2*)&sS[jj * DD + kq * 4];
                unsigned long long aA = bcast2(avA.x);
                unsigned long long aB = bcast2(avB.x);
                relu_mad4(accA0, accA1, sv.x, sv.y, tA.x, tA.y, aA);
                relu_mad4(accB0, accB1, sv.x, sv.y, tB.x, tB.y, aB);
            }
            {
                ulonglong2 sv = *(const ulonglong2*)&sS[(jj + 1) * DD + kq * 4];
                unsigned long long aA = bcast2(avA.y);
                unsigned long long aB = bcast2(avB.y);
                relu_mad4(accA0, accA1, sv.x, sv.y, tA.x, tA.y, aA);
                relu_mad4(accB0, accB1, sv.x, sv.y, tB.x, tB.y, aB);
            }
        }
        __syncthreads();
    }

    {
        ulonglong2 oA; oA.x = accA0; oA.y = accA1;
        ulonglong2 oB; oB.x = accB0; oB.y = accB1;
        size_t base = (((size_t)js * BB + b) * NN + i0) * DD;
        *(ulonglong2*)&g_v[base + (size_t)iA * DD + kq * 4] = oA;
        *(ulonglong2*)&g_v[base + (size_t)iB * DD + kq * 4] = oB;
    }
}

// ============ K3: tiled GEMM: out = ES + (sum_js v) @ W2 + b2 ============
__global__ void __launch_bounds__(256) k_epi(const float* __restrict__ ES,
                                             const float* __restrict__ W2,
                                             const float* __restrict__ b2,
                                             float* __restrict__ out_state)
{
    __shared__ float sV[GBK][GBM + APAD];
    __shared__ float sW[GBK][GBN];

    int tid = threadIdx.x;
    int tx  = tid & 15;
    int ty  = tid >> 4;
    int r0  = blockIdx.x * GBM;
    int c0  = blockIdx.y * GBN;

    int lrow = tid >> 3;
    int lk4  = tid & 7;
    int wk   = tid >> 4;
    int wc4  = tid & 15;

    const size_t PSTRIDE = (size_t)BB * NN * DD;

    float4 vA[2], wB[2];
    {
        #pragma unroll
        for (int q = 0; q < 2; q++) {
            size_t off = ((size_t)(r0 + lrow + q * 32)) * DD + lk4 * 4;
            float4 a = *(const float4*)&g_v[off];
            float4 c = *(const float4*)&g_v[off + PSTRIDE];
            float4 d = *(const float4*)&g_v[off + 2 * PSTRIDE];
            float4 e = *(const float4*)&g_v[off + 3 * PSTRIDE];
            a.x += c.x; a.y += c.y; a.z += c.z; a.w += c.w;
            d.x += e.x; d.y += e.y; d.z += e.z; d.w += e.w;
            a.x += d.x; a.y += d.y; a.z += d.z; a.w += d.w;
            vA[q] = a;
        }
        wB[0] = *(const float4*)&W2[(size_t)(wk     ) * DD + c0 + wc4 * 4];
        wB[1] = *(const float4*)&W2[(size_t)(wk + 16) * DD + c0 + wc4 * 4];
    }

    unsigned long long acc[4][2];
    #pragma unroll
    for (int r = 0; r < 4; r++) { acc[r][0] = 0ull; acc[r][1] = 0ull; }

    for (int kt = 0; kt < DD; kt += GBK) {
        if (kt) __syncthreads();
        #pragma unroll
        for (int q = 0; q < 2; q++) {
            sV[lk4 * 4 + 0][lrow + q * 32] = (&vA[q].x)[0];
            sV[lk4 * 4 + 1][lrow + q * 32] = (&vA[q].x)[1];
            sV[lk4 * 4 + 2][lrow + q * 32] = (&vA[q].x)[2];
            sV[lk4 * 4 + 3][lrow + q * 32] = (&vA[q].x)[3];
        }
        *(float4*)&sW[wk][wc4 * 4]      = wB[0];
        *(float4*)&sW[wk + 16][wc4 * 4] = wB[1];
        __syncthreads();

        if (kt + GBK < DD) {
            int kn = kt + GBK;
            #pragma unroll
            for (int q = 0; q < 2; q++) {
                size_t off = ((size_t)(r0 + lrow + q * 32)) * DD + kn + lk4 * 4;
                float4 a = *(const float4*)&g_v[off];
                float4 c = *(const float4*)&g_v[off + PSTRIDE];
                float4 d = *(const float4*)&g_v[off + 2 * PSTRIDE];
                float4 e = *(const float4*)&g_v[off + 3 * PSTRIDE];
                a.x += c.x; a.y += c.y; a.z += c.z; a.w += c.w;
                d.x += e.x; d.y += e.y; d.z += e.z; d.w += e.w;
                a.x += d.x; a.y += d.y; a.z += d.z; a.w += d.w;
                vA[q] = a;
            }
            wB[0] = *(const float4*)&W2[(size_t)(kn + wk     ) * DD + c0 + wc4 * 4];
            wB[1] = *(const float4*)&W2[(size_t)(kn + wk + 16) * DD + c0 + wc4 * 4];
        }

        #pragma unroll 8
        for (int k = 0; k < GBK; k++) {
            float4 e4 = *(const float4*)&sV[k][ty * 4];
            ulonglong2 w2 = *(const ulonglong2*)&sW[k][tx * 4];
            unsigned long long e0 = bcast2(e4.x);
            unsigned long long e1 = bcast2(e4.y);
            unsigned long long e2 = bcast2(e4.z);
            unsigned long long e3 = bcast2(e4.w);
            fma2acc(acc[0][0], e0, w2.x); fma2acc(acc[0][1], e0, w2.y);
            fma2acc(acc[1][0], e1, w2.x); fma2acc(acc[1][1], e1, w2.y);
            fma2acc(acc[2][0], e2, w2.x); fma2acc(acc[2][1], e2, w2.y);
            fma2acc(acc[3][0], e3, w2.x); fma2acc(acc[3][1], e3, w2.y);
        }
    }

    float4 bias = *(const float4*)&b2[c0 + tx * 4];
    #pragma unroll
    for (int r = 0; r < 4; r++) {
        size_t row = (size_t)(r0 + ty * 4 + r);
        float4 es = *(const float4*)&ES[row * DD + c0 + tx * 4];
        float2 p0 = unpack2(acc[r][0]);
        float2 p1 = unpack2(acc[r][1]);
        float4 o;
        o.x = es.x + p0.x + bias.x;
        o.y = es.y + p0.y + bias.y;
        o.z = es.z + p1.x + bias.z;
        o.w = es.w + p1.y + bias.w;
        *(float4*)&out_state[row * DD + c0 + tx * 4] = o;
    }
}

// ---------------- launch ----------------
extern "C" void kernel_launch(void* const* d_in, const int* in_sizes, int n_in,
                              void* d_out, int out_size)
{
    const float* ES  = (const float*)d_in[0];
    const float* Wp  = (const float*)d_in[1];
    const float* bp  = (const float*)d_in[2];
    const float* EL  = (const float*)d_in[3];
    const float* W1  = (const float*)d_in[4];
    const float* b1  = (const float*)d_in[5];
    const float* W2  = (const float*)d_in[6];
    const float* b2  = (const float*)d_in[7];
    const float* UN  = (const float*)d_in[8];

    float* out_state = (float*)d_out;
    float* out_A     = (float*)d_out + (size_t)BB * NN * DD;

    k_combine<<<DD + 1, 256>>>(Wp, bp, W1, b1);
    k_proj<<<dim3((BB * NN) / GBM, 256 / GBN), 256>>>(ES);
    k_main<<<dim3(NN / TI, BB, JS), 256>>>(EL, UN, out_A);
    k_epi<<<dim3((BB * NN) / GBM, DD / GBN), 256>>>(ES, W2, b2, out_state);
}